// round 1
// baseline (speedup 1.0000x reference)
#include <cuda_runtime.h>
#include <math.h>

#define BATCH 512
#define NV 6890
#define NBETA 10
#define NJOINT 24

__constant__ int c_parents[NJOINT] = {-1,0,0,0,1,2,3,4,5,6,7,8,9,9,9,12,13,14,16,17,18,19,20,21};

// Scratch (no allocations allowed): precomputed joint regressors + per-batch A matrices
__device__ float  g_JrVt[NJOINT * 3];            // Jr @ v_template         [24,3]
__device__ float  g_JrS [NJOINT * 3 * NBETA];    // Jr @ shapedirs          [24,3,10]
__device__ float4 g_A4  [BATCH * NJOINT * 3];    // A matrices, 3x float4 (rows of 3x4) per joint

// ---------------------------------------------------------------------------
// Kernel A: precompute JrVt[j,k] = sum_v Jr[j,v]*v_template[v,k]
//           and      JrS[j,k,l] = sum_v Jr[j,v]*shapedirs[v,k,l]
// One block per joint j; 256 threads reduce over V.
// ---------------------------------------------------------------------------
__global__ void __launch_bounds__(256) kernelA(
    const float* __restrict__ shapedirs,   // [V,3,10]
    const float* __restrict__ v_template,  // [V,3]
    const float* __restrict__ Jr)          // [24,V]
{
    int j = blockIdx.x;
    int tid = threadIdx.x;

    float acc[33];
#pragma unroll
    for (int i = 0; i < 33; i++) acc[i] = 0.f;

    for (int v = tid; v < NV; v += 256) {
        float wj = Jr[j * NV + v];
        const float2* sd2 = (const float2*)(shapedirs + (size_t)v * 30);
        float sd[30];
#pragma unroll
        for (int q = 0; q < 15; q++) { float2 t2 = sd2[q]; sd[2*q] = t2.x; sd[2*q+1] = t2.y; }
#pragma unroll
        for (int k = 0; k < 3; k++) {
            acc[k * 11] += wj * v_template[v * 3 + k];
#pragma unroll
            for (int l = 0; l < NBETA; l++)
                acc[k * 11 + 1 + l] += wj * sd[k * 10 + l];
        }
    }

    // warp reduce all 33 accumulators
#pragma unroll
    for (int i = 0; i < 33; i++) {
#pragma unroll
        for (int o = 16; o > 0; o >>= 1)
            acc[i] += __shfl_xor_sync(0xffffffffu, acc[i], o);
    }

    __shared__ float part[8][33];
    int warp = tid >> 5, lane = tid & 31;
    if (lane == 0) {
#pragma unroll
        for (int i = 0; i < 33; i++) part[warp][i] = acc[i];
    }
    __syncthreads();
    if (tid < 33) {
        float s = 0.f;
#pragma unroll
        for (int ww = 0; ww < 8; ww++) s += part[ww][tid];
        int k = tid / 11, r = tid % 11;
        if (r == 0) g_JrVt[j * 3 + k] = s;
        else        g_JrS[(j * 3 + k) * NBETA + (r - 1)] = s;
    }
}

// ---------------------------------------------------------------------------
// Kernel B: per-batch joints, rodrigues, kinematic chain, A matrices.
// One warp per batch element.
// ---------------------------------------------------------------------------
__global__ void __launch_bounds__(32) kernelB(
    const float* __restrict__ betas,      // [B,11]
    const float* __restrict__ body_pose,  // [B,69]
    const float* __restrict__ global_or,  // [B,3]
    float* __restrict__ d_out)            // J_transformed region at offset B*V*3
{
    int b = blockIdx.x;
    int lane = threadIdx.x;

    __shared__ float sB[11];
    __shared__ float sLoc[NJOINT][12];     // local 3x4 [R|t_rel]
    __shared__ float sWorld[NJOINT][12];   // world 3x4
    __shared__ float sJ[NJOINT][3];

    if (lane < 11) sB[lane] = betas[b * 11 + lane];
    __syncwarp();

    // Joints from precomputed regressors
    if (lane < NJOINT) {
        int j = lane;
        float s0 = sB[0];
#pragma unroll
        for (int k = 0; k < 3; k++) {
            float val = g_JrVt[j * 3 + k];
#pragma unroll
            for (int l = 0; l < NBETA; l++)
                val += sB[1 + l] * g_JrS[(j * 3 + k) * NBETA + l];
            sJ[j][k] = val * s0;
        }
    }
    __syncwarp();

    // Rodrigues + relative translation -> local transforms
    if (lane < NJOINT) {
        int j = lane;
        float r0, r1, r2;
        if (j == 0) {
            r0 = global_or[b * 3 + 0]; r1 = global_or[b * 3 + 1]; r2 = global_or[b * 3 + 2];
        } else {
            const float* pp = body_pose + b * 69 + (j - 1) * 3;
            r0 = pp[0]; r1 = pp[1]; r2 = pp[2];
        }
        float a0 = r0 + 1e-8f, a1 = r1 + 1e-8f, a2 = r2 + 1e-8f;
        float angle = sqrtf(a0 * a0 + a1 * a1 + a2 * a2);
        float inv = 1.0f / angle;
        float rx = r0 * inv, ry = r1 * inv, rz = r2 * inv;
        float c = cosf(angle), s = sinf(angle), t = 1.f - c;
        sLoc[j][0]  = 1.f - t * (ry * ry + rz * rz);
        sLoc[j][1]  = -s * rz + t * rx * ry;
        sLoc[j][2]  =  s * ry + t * rx * rz;
        sLoc[j][4]  =  s * rz + t * rx * ry;
        sLoc[j][5]  = 1.f - t * (rx * rx + rz * rz);
        sLoc[j][6]  = -s * rx + t * ry * rz;
        sLoc[j][8]  = -s * ry + t * rx * rz;
        sLoc[j][9]  =  s * rx + t * ry * rz;
        sLoc[j][10] = 1.f - t * (rx * rx + ry * ry);
        int p = c_parents[j];
#pragma unroll
        for (int k = 0; k < 3; k++)
            sLoc[j][k * 4 + 3] = (p < 0) ? sJ[j][k] : (sJ[j][k] - sJ[p][k]);
    }
    __syncwarp();

    // Kinematic chain: 12 lanes compute the 12 entries of each world 3x4
    if (lane < 12) sWorld[0][lane] = sLoc[0][lane];
    __syncwarp();
    for (int j = 1; j < NJOINT; j++) {
        if (lane < 12) {
            int r = lane >> 2, c = lane & 3;
            int p = c_parents[j];
            float val = sWorld[p][r * 4 + 0] * sLoc[j][0 * 4 + c]
                      + sWorld[p][r * 4 + 1] * sLoc[j][1 * 4 + c]
                      + sWorld[p][r * 4 + 2] * sLoc[j][2 * 4 + c];
            if (c == 3) val += sWorld[p][r * 4 + 3];
            sWorld[j][lane] = val;
        }
        __syncwarp();
    }

    // Outputs: J_transformed and A = [R | t - R*J]
    float* Jout = d_out + (size_t)BATCH * NV * 3;
    if (lane < NJOINT) {
        int j = lane;
        float jx = sJ[j][0], jy = sJ[j][1], jz = sJ[j][2];
        float* Aout = (float*)g_A4 + (size_t)b * 288 + j * 12;
#pragma unroll
        for (int r = 0; r < 3; r++) {
            float m0 = sWorld[j][r * 4 + 0];
            float m1 = sWorld[j][r * 4 + 1];
            float m2 = sWorld[j][r * 4 + 2];
            float m3 = sWorld[j][r * 4 + 3];
            Jout[(size_t)b * NJOINT * 3 + j * 3 + r] = m3;
            Aout[r * 4 + 0] = m0;
            Aout[r * 4 + 1] = m1;
            Aout[r * 4 + 2] = m2;
            Aout[r * 4 + 3] = m3 - (m0 * jx + m1 * jy + m2 * jz);
        }
    }
}

// ---------------------------------------------------------------------------
// Kernel C: fused shape blend + LBS. One thread per (b, v).
// ---------------------------------------------------------------------------
__global__ void __launch_bounds__(256) kernelC(
    const float* __restrict__ betas,       // [B,11]
    const float* __restrict__ transl,      // [B,3]
    const float* __restrict__ shapedirs,   // [V,3,10]
    const float* __restrict__ v_template,  // [V,3]
    const float* __restrict__ W,           // [V,24]
    float* __restrict__ out)               // verts [B,V,3]
{
    int b = blockIdx.y;
    int tid = threadIdx.x;
    int v = blockIdx.x * 256 + tid;

    __shared__ float4 sA[NJOINT * 3];   // 72 float4 = A[b] (24 joints x 3 rows)
    __shared__ float  sBet[11];
    __shared__ float  sT[3];

    if (tid < 72) sA[tid] = g_A4[(size_t)b * 72 + tid];
    if (tid >= 96 && tid < 107) sBet[tid - 96] = betas[b * 11 + (tid - 96)];
    if (tid >= 128 && tid < 131) sT[tid - 128] = transl[b * 3 + (tid - 128)];
    __syncthreads();

    if (v >= NV) return;

    float bet[11];
#pragma unroll
    for (int i = 0; i < 11; i++) bet[i] = sBet[i];

    // v_shaped for this vertex
    float p0, p1, p2;
    {
        const float2* sd2 = (const float2*)(shapedirs + (size_t)v * 30);
        float sd[30];
#pragma unroll
        for (int q = 0; q < 15; q++) { float2 t2 = sd2[q]; sd[2*q] = t2.x; sd[2*q+1] = t2.y; }
        float q0[3];
#pragma unroll
        for (int k = 0; k < 3; k++) {
            float val = v_template[v * 3 + k];
#pragma unroll
            for (int l = 0; l < NBETA; l++)
                val += bet[1 + l] * sd[k * 10 + l];
            q0[k] = val * bet[0];
        }
        p0 = q0[0]; p1 = q0[1]; p2 = q0[2];
    }

    // LBS weights (contiguous, 16B-aligned: 24 floats = 96 bytes)
    float wv[NJOINT];
    const float4* Wp = (const float4*)(W + (size_t)v * NJOINT);
#pragma unroll
    for (int q = 0; q < 6; q++) {
        float4 t4 = Wp[q];
        wv[4*q] = t4.x; wv[4*q+1] = t4.y; wv[4*q+2] = t4.z; wv[4*q+3] = t4.w;
    }

    // T = sum_n w_n * A_n  (3x4 accumulation)
    float T[12];
#pragma unroll
    for (int i = 0; i < 12; i++) T[i] = 0.f;
#pragma unroll
    for (int n = 0; n < NJOINT; n++) {
        float w = wv[n];
        float4 a0 = sA[n * 3 + 0];
        float4 a1 = sA[n * 3 + 1];
        float4 a2 = sA[n * 3 + 2];
        T[0] += w * a0.x; T[1]  += w * a0.y; T[2]  += w * a0.z; T[3]  += w * a0.w;
        T[4] += w * a1.x; T[5]  += w * a1.y; T[6]  += w * a1.z; T[7]  += w * a1.w;
        T[8] += w * a2.x; T[9]  += w * a2.y; T[10] += w * a2.z; T[11] += w * a2.w;
    }

    size_t base = ((size_t)b * NV + v) * 3;
    out[base + 0] = T[0] * p0 + T[1] * p1 + T[2]  * p2 + T[3]  + sT[0];
    out[base + 1] = T[4] * p0 + T[5] * p1 + T[6]  * p2 + T[7]  + sT[1];
    out[base + 2] = T[8] * p0 + T[9] * p1 + T[10] * p2 + T[11] + sT[2];
}

extern "C" void kernel_launch(void* const* d_in, const int* in_sizes, int n_in,
                              void* d_out, int out_size)
{
    const float* betas      = (const float*)d_in[0];
    const float* body_pose  = (const float*)d_in[1];
    const float* global_or  = (const float*)d_in[2];
    const float* transl     = (const float*)d_in[3];
    const float* shapedirs  = (const float*)d_in[4];
    const float* v_template = (const float*)d_in[5];
    const float* Jr         = (const float*)d_in[6];
    const float* W          = (const float*)d_in[7];
    float* out = (float*)d_out;

    kernelA<<<NJOINT, 256>>>(shapedirs, v_template, Jr);
    kernelB<<<BATCH, 32>>>(betas, body_pose, global_or, out);
    dim3 grid((NV + 255) / 256, BATCH);
    kernelC<<<grid, 256>>>(betas, transl, shapedirs, v_template, W, out);
}

// round 2
// speedup vs baseline: 1.4456x; 1.4456x over previous
#include <cuda_runtime.h>
#include <math.h>

#define BATCH 512
#define NV 6890
#define NBETA 10
#define NJOINT 24

#define ACH 8            // kernelA V-chunks
#define ACH_LEN 862      // ceil(6890/8)

#define CBLK 128         // kernelC threads (= vertices per block)
#define NBCH 16          // kernelC batch-chunks
#define BPB (BATCH/NBCH) // 32 batches per block

__constant__ int c_parents[NJOINT] = {-1,0,0,0,1,2,3,4,5,6,7,8,9,9,9,12,13,14,16,17,18,19,20,21};

// Device scratch (no allocations allowed)
__device__ float  g_part[NJOINT][ACH][33];     // partial joint-regressor sums
__device__ float4 g_A4  [BATCH * NJOINT * 3];  // per-batch A matrices (3x4 rows as float4)

// ---- f32x2 packed-math helpers (sm_10x FFMA2) ------------------------------
__device__ __forceinline__ unsigned long long f2pack(float lo, float hi) {
    unsigned long long r;
    asm("mov.b64 %0, {%1, %2};" : "=l"(r) : "f"(lo), "f"(hi));
    return r;
}
__device__ __forceinline__ void f2unpack(unsigned long long v, float& lo, float& hi) {
    asm("mov.b64 {%0, %1}, %2;" : "=f"(lo), "=f"(hi) : "l"(v));
}
__device__ __forceinline__ unsigned long long ffma2(unsigned long long a,
                                                    unsigned long long b,
                                                    unsigned long long c) {
    unsigned long long d;
    asm("fma.rn.f32x2 %0, %1, %2, %3;" : "=l"(d) : "l"(a), "l"(b), "l"(c));
    return d;
}

// ---------------------------------------------------------------------------
// Kernel A: partial sums of Jr @ [v_template | shapedirs] over a V-chunk.
// grid = (24 joints, 8 chunks), block = 256.
// ---------------------------------------------------------------------------
__global__ void __launch_bounds__(256) kernelA(
    const float* __restrict__ shapedirs,   // [V,3,10]
    const float* __restrict__ v_template,  // [V,3]
    const float* __restrict__ Jr)          // [24,V]
{
    int j = blockIdx.x;
    int c = blockIdx.y;
    int tid = threadIdx.x;

    int v0 = c * ACH_LEN;
    int v1 = min(v0 + ACH_LEN, NV);

    float acc[33];
#pragma unroll
    for (int i = 0; i < 33; i++) acc[i] = 0.f;

    for (int v = v0 + tid; v < v1; v += 256) {
        float wj = Jr[j * NV + v];
        const float2* sd2 = (const float2*)(shapedirs + (size_t)v * 30);
        float sd[30];
#pragma unroll
        for (int q = 0; q < 15; q++) { float2 t2 = sd2[q]; sd[2*q] = t2.x; sd[2*q+1] = t2.y; }
#pragma unroll
        for (int k = 0; k < 3; k++) {
            acc[k * 11] += wj * v_template[v * 3 + k];
#pragma unroll
            for (int l = 0; l < NBETA; l++)
                acc[k * 11 + 1 + l] += wj * sd[k * 10 + l];
        }
    }

#pragma unroll
    for (int i = 0; i < 33; i++) {
#pragma unroll
        for (int o = 16; o > 0; o >>= 1)
            acc[i] += __shfl_xor_sync(0xffffffffu, acc[i], o);
    }

    __shared__ float part[8][33];
    int warp = tid >> 5, lane = tid & 31;
    if (lane == 0) {
#pragma unroll
        for (int i = 0; i < 33; i++) part[warp][i] = acc[i];
    }
    __syncthreads();
    if (tid < 33) {
        float s = 0.f;
#pragma unroll
        for (int ww = 0; ww < 8; ww++) s += part[ww][tid];
        g_part[j][c][tid] = s;
    }
}

// ---------------------------------------------------------------------------
// Kernel B: per-batch joints, rodrigues, kinematic chain, A matrices.
// One warp per batch element.
// ---------------------------------------------------------------------------
__global__ void __launch_bounds__(32) kernelB(
    const float* __restrict__ betas,      // [B,11]
    const float* __restrict__ body_pose,  // [B,69]
    const float* __restrict__ global_or,  // [B,3]
    float* __restrict__ d_out)            // J_transformed region at offset B*V*3
{
    int b = blockIdx.x;
    int lane = threadIdx.x;

    __shared__ float sB[11];
    __shared__ float sLoc[NJOINT][12];
    __shared__ float sWorld[NJOINT][12];
    __shared__ float sJ[NJOINT][3];

    if (lane < 11) sB[lane] = betas[b * 11 + lane];
    __syncwarp();

    // Joints from partial regressor sums
    if (lane < NJOINT) {
        int j = lane;
        float tot[33];
#pragma unroll
        for (int i = 0; i < 33; i++) {
            float s = 0.f;
#pragma unroll
            for (int cc = 0; cc < ACH; cc++) s += g_part[j][cc][i];
            tot[i] = s;
        }
        float s0 = sB[0];
#pragma unroll
        for (int k = 0; k < 3; k++) {
            float val = tot[k * 11];
#pragma unroll
            for (int l = 0; l < NBETA; l++)
                val += sB[1 + l] * tot[k * 11 + 1 + l];
            sJ[j][k] = val * s0;
        }
    }
    __syncwarp();

    if (lane < NJOINT) {
        int j = lane;
        float r0, r1, r2;
        if (j == 0) {
            r0 = global_or[b * 3 + 0]; r1 = global_or[b * 3 + 1]; r2 = global_or[b * 3 + 2];
        } else {
            const float* pp = body_pose + b * 69 + (j - 1) * 3;
            r0 = pp[0]; r1 = pp[1]; r2 = pp[2];
        }
        float a0 = r0 + 1e-8f, a1 = r1 + 1e-8f, a2 = r2 + 1e-8f;
        float angle = sqrtf(a0 * a0 + a1 * a1 + a2 * a2);
        float inv = 1.0f / angle;
        float rx = r0 * inv, ry = r1 * inv, rz = r2 * inv;
        float c = cosf(angle), s = sinf(angle), t = 1.f - c;
        sLoc[j][0]  = 1.f - t * (ry * ry + rz * rz);
        sLoc[j][1]  = -s * rz + t * rx * ry;
        sLoc[j][2]  =  s * ry + t * rx * rz;
        sLoc[j][4]  =  s * rz + t * rx * ry;
        sLoc[j][5]  = 1.f - t * (rx * rx + rz * rz);
        sLoc[j][6]  = -s * rx + t * ry * rz;
        sLoc[j][8]  = -s * ry + t * rx * rz;
        sLoc[j][9]  =  s * rx + t * ry * rz;
        sLoc[j][10] = 1.f - t * (rx * rx + ry * ry);
        int p = c_parents[j];
#pragma unroll
        for (int k = 0; k < 3; k++)
            sLoc[j][k * 4 + 3] = (p < 0) ? sJ[j][k] : (sJ[j][k] - sJ[p][k]);
    }
    __syncwarp();

    if (lane < 12) sWorld[0][lane] = sLoc[0][lane];
    __syncwarp();
    for (int j = 1; j < NJOINT; j++) {
        if (lane < 12) {
            int r = lane >> 2, cc = lane & 3;
            int p = c_parents[j];
            float val = sWorld[p][r * 4 + 0] * sLoc[j][0 * 4 + cc]
                      + sWorld[p][r * 4 + 1] * sLoc[j][1 * 4 + cc]
                      + sWorld[p][r * 4 + 2] * sLoc[j][2 * 4 + cc];
            if (cc == 3) val += sWorld[p][r * 4 + 3];
            sWorld[j][lane] = val;
        }
        __syncwarp();
    }

    float* Jout = d_out + (size_t)BATCH * NV * 3;
    if (lane < NJOINT) {
        int j = lane;
        float jx = sJ[j][0], jy = sJ[j][1], jz = sJ[j][2];
        float* Aout = (float*)g_A4 + (size_t)b * 288 + j * 12;
#pragma unroll
        for (int r = 0; r < 3; r++) {
            float m0 = sWorld[j][r * 4 + 0];
            float m1 = sWorld[j][r * 4 + 1];
            float m2 = sWorld[j][r * 4 + 2];
            float m3 = sWorld[j][r * 4 + 3];
            Jout[(size_t)b * NJOINT * 3 + j * 3 + r] = m3;
            Aout[r * 4 + 0] = m0;
            Aout[r * 4 + 1] = m1;
            Aout[r * 4 + 2] = m2;
            Aout[r * 4 + 3] = m3 - (m0 * jx + m1 * jy + m2 * jz);
        }
    }
}

// ---------------------------------------------------------------------------
// Kernel C: fused shape blend + LBS, batch-loop inverted.
// Block owns CBLK vertices, loops over BPB batches. Per-vertex data stays in
// registers; A[b] staged in shared; T accumulation in packed f32x2.
// ---------------------------------------------------------------------------
__global__ void __launch_bounds__(CBLK) kernelC(
    const float* __restrict__ betas,       // [B,11]
    const float* __restrict__ transl,      // [B,3]
    const float* __restrict__ shapedirs,   // [V,3,10]
    const float* __restrict__ v_template,  // [V,3]
    const float* __restrict__ W,           // [V,24]
    float* __restrict__ out)               // verts [B,V,3]
{
    int tid = threadIdx.x;
    int v = blockIdx.x * CBLK + tid;
    int b0 = blockIdx.y * BPB;
    bool valid = (v < NV);
    int vc = valid ? v : (NV - 1);

    __shared__ float4 sA[NJOINT * 3];   // A[b]: 72 float4
    __shared__ float  sBT[14];          // betas[0..10], transl[0..2]

    // --- per-vertex constants (live across the whole b-loop) ---
    float sd[30];
    {
        const float2* sd2 = (const float2*)(shapedirs + (size_t)vc * 30);
#pragma unroll
        for (int q = 0; q < 15; q++) { float2 t2 = sd2[q]; sd[2*q] = t2.x; sd[2*q+1] = t2.y; }
    }
    float vt0 = v_template[vc * 3 + 0];
    float vt1 = v_template[vc * 3 + 1];
    float vt2 = v_template[vc * 3 + 2];

    unsigned long long wp[NJOINT];      // (w,w) packed per joint
    {
        const float4* Wp = (const float4*)(W + (size_t)vc * NJOINT);
#pragma unroll
        for (int q = 0; q < 6; q++) {
            float4 t4 = Wp[q];
            wp[4*q + 0] = f2pack(t4.x, t4.x);
            wp[4*q + 1] = f2pack(t4.y, t4.y);
            wp[4*q + 2] = f2pack(t4.z, t4.z);
            wp[4*q + 3] = f2pack(t4.w, t4.w);
        }
    }

    const ulonglong2* A2 = (const ulonglong2*)sA;

    for (int ib = 0; ib < BPB; ib++) {
        int b = b0 + ib;
        __syncthreads();   // previous iteration's reads of sA done
        if (tid < 72)                  sA[tid] = g_A4[(size_t)b * 72 + tid];
        else if (tid < 83)             sBT[tid - 72] = betas[b * 11 + (tid - 72)];
        else if (tid < 86)             sBT[11 + tid - 83] = transl[b * 3 + (tid - 83)];
        __syncthreads();

        // shape blend for this (b, v)
        float be0 = sBT[0];
        float p0, p1, p2;
        {
            float q0 = vt0, q1 = vt1, q2 = vt2;
#pragma unroll
            for (int l = 0; l < NBETA; l++) {
                float bl = sBT[1 + l];
                q0 = fmaf(bl, sd[l],      q0);
                q1 = fmaf(bl, sd[10 + l], q1);
                q2 = fmaf(bl, sd[20 + l], q2);
            }
            p0 = q0 * be0; p1 = q1 * be0; p2 = q2 * be0;
        }

        // T = sum_n w_n * A_n, packed f32x2 (6 pairs = 12 floats of the 3x4)
        unsigned long long T0 = 0ull, T1 = 0ull, T2 = 0ull,
                           T3 = 0ull, T4 = 0ull, T5 = 0ull;
#pragma unroll
        for (int n = 0; n < NJOINT; n++) {
            ulonglong2 q0 = A2[n * 3 + 0];
            ulonglong2 q1 = A2[n * 3 + 1];
            ulonglong2 q2 = A2[n * 3 + 2];
            unsigned long long w = wp[n];
            T0 = ffma2(w, q0.x, T0); T1 = ffma2(w, q0.y, T1);
            T2 = ffma2(w, q1.x, T2); T3 = ffma2(w, q1.y, T3);
            T4 = ffma2(w, q2.x, T4); T5 = ffma2(w, q2.y, T5);
        }

        if (valid) {
            float t00, t01, t02, t03, t10, t11, t12, t13, t20, t21, t22, t23;
            f2unpack(T0, t00, t01); f2unpack(T1, t02, t03);
            f2unpack(T2, t10, t11); f2unpack(T3, t12, t13);
            f2unpack(T4, t20, t21); f2unpack(T5, t22, t23);
            size_t base = ((size_t)b * NV + v) * 3;
            out[base + 0] = fmaf(t00, p0, fmaf(t01, p1, fmaf(t02, p2, t03 + sBT[11])));
            out[base + 1] = fmaf(t10, p0, fmaf(t11, p1, fmaf(t12, p2, t13 + sBT[12])));
            out[base + 2] = fmaf(t20, p0, fmaf(t21, p1, fmaf(t22, p2, t23 + sBT[13])));
        }
    }
}

extern "C" void kernel_launch(void* const* d_in, const int* in_sizes, int n_in,
                              void* d_out, int out_size)
{
    const float* betas      = (const float*)d_in[0];
    const float* body_pose  = (const float*)d_in[1];
    const float* global_or  = (const float*)d_in[2];
    const float* transl     = (const float*)d_in[3];
    const float* shapedirs  = (const float*)d_in[4];
    const float* v_template = (const float*)d_in[5];
    const float* Jr         = (const float*)d_in[6];
    const float* W          = (const float*)d_in[7];
    float* out = (float*)d_out;

    dim3 gridA(NJOINT, ACH);
    kernelA<<<gridA, 256>>>(shapedirs, v_template, Jr);
    kernelB<<<BATCH, 32>>>(betas, body_pose, global_or, out);
    dim3 gridC((NV + CBLK - 1) / CBLK, NBCH);
    kernelC<<<gridC, CBLK>>>(betas, transl, shapedirs, v_template, W, out);
}